// round 1
// baseline (speedup 1.0000x reference)
#include <cuda_runtime.h>

#define NPTS 1000000
#define DIMX 300
#define DIMY 300
#define DIMZ 300
#define RNK  48
#define NC   27

// Transposed scratch: planes [H*W][R], vectors [L][R]
__device__ float g_xyT[DIMX * DIMY * RNK];
__device__ float g_xzT[DIMX * DIMZ * RNK];
__device__ float g_yzT[DIMY * DIMZ * RNK];
__device__ float g_xvT[DIMX * RNK];
__device__ float g_yvT[DIMY * RNK];
__device__ float g_zvT[DIMZ * RNK];

// src: [RNK][cells]  ->  dst: [cells][RNK]
__global__ void __launch_bounds__(128) transpose_kernel(
    const float* __restrict__ src, float* __restrict__ dst, int cells)
{
    __shared__ float tile[RNK][129];
    int base = blockIdx.x * 128;
    int t = threadIdx.x;
    int nc = cells - base;
    if (nc > 128) nc = 128;

    #pragma unroll
    for (int r = 0; r < RNK; r++) {
        if (t < nc) tile[r][t] = src[r * cells + base + t];
    }
    __syncthreads();
    for (int i = t; i < nc * RNK; i += 128) {
        int cl = i / RNK;
        int r  = i - cl * RNK;
        dst[(base + cl) * RNK + r] = tile[r][cl];
    }
}

// One segment: bilinear(plane) * lerp(vec), fused into 28-wide FMA accumulation
// against sF rows [segbase .. segbase+47], each row padded to 28 floats.
__device__ __forceinline__ void do_seg(
    const float4* __restrict__ p00, const float4* __restrict__ p01,
    const float4* __restrict__ p10, const float4* __restrict__ p11,
    const float4* __restrict__ v0p, const float4* __restrict__ v1p,
    float fh, float fw, float fv,
    const float* __restrict__ sFrow, float* acc)
{
    float w00 = (1.0f - fh) * (1.0f - fw);
    float w01 = (1.0f - fh) * fw;
    float w10 = fh * (1.0f - fw);
    float w11 = fh * fw;

    #pragma unroll 2
    for (int k = 0; k < RNK / 4; k++) {
        float4 a = p00[k];
        float4 b = p01[k];
        float4 c = p10[k];
        float4 d = p11[k];
        float4 u = v0p[k];
        float4 w = v1p[k];

        float fe0 = (w00 * a.x + w01 * b.x + w10 * c.x + w11 * d.x) * fmaf(fv, w.x - u.x, u.x);
        float fe1 = (w00 * a.y + w01 * b.y + w10 * c.y + w11 * d.y) * fmaf(fv, w.y - u.y, u.y);
        float fe2 = (w00 * a.z + w01 * b.z + w10 * c.z + w11 * d.z) * fmaf(fv, w.z - u.z, u.z);
        float fe3 = (w00 * a.w + w01 * b.w + w10 * c.w + w11 * d.w) * fmaf(fv, w.w - u.w, u.w);
        float fe[4] = {fe0, fe1, fe2, fe3};

        #pragma unroll
        for (int j = 0; j < 4; j++) {
            const float4* Fr = (const float4*)(sFrow + (k * 4 + j) * 28);
            float f = fe[j];
            #pragma unroll
            for (int m = 0; m < 7; m++) {
                float4 q = Fr[m];
                acc[m * 4 + 0] = fmaf(f, q.x, acc[m * 4 + 0]);
                acc[m * 4 + 1] = fmaf(f, q.y, acc[m * 4 + 1]);
                acc[m * 4 + 2] = fmaf(f, q.z, acc[m * 4 + 2]);
                acc[m * 4 + 3] = fmaf(f, q.w, acc[m * 4 + 3]);
            }
        }
    }
}

__device__ __forceinline__ void prep_coord(float g, int L, int& i0, int& i1, float& f)
{
    float t  = (g + 1.0f) * 0.5f;
    float ih = t * (float)(L - 1);
    int i = (int)floorf(ih);
    i = max(0, min(i, L - 1));
    i0 = i;
    i1 = min(i + 1, L - 1);
    f = ih - (float)i;
}

__global__ void __launch_bounds__(256) sample_kernel(
    const float* __restrict__ xyz, const float* __restrict__ fvec,
    float* __restrict__ out)
{
    // sBuf: first used as padded F (144 rows x 28 floats = 4032 floats),
    // then reused as the output staging buffer (256 x 27 = 6912 floats).
    __shared__ __align__(16) float sBuf[256 * NC];
    __shared__ float sXYZ[256 * 3];

    int tid  = threadIdx.x;
    int base = blockIdx.x * 256;

    // Load f_vec into smem with rows padded 27 -> 28 (16B-aligned rows, pad = 0)
    for (int i = tid; i < 144 * 28; i += 256) {
        int r = i / 28;
        int c = i - r * 28;
        sBuf[i] = (c < NC) ? fvec[r * NC + c] : 0.0f;
    }
    // Stage xyz coalesced
    for (int i = tid; i < 768; i += 256) {
        int g = base * 3 + i;
        sXYZ[i] = (g < NPTS * 3) ? xyz[g] : 0.25f;
    }
    __syncthreads();

    int p = base + tid;
    float x = sXYZ[tid * 3 + 0];
    float y = sXYZ[tid * 3 + 1];
    float z = sXYZ[tid * 3 + 2];

    float gx = x * 2.0f - 1.0f;
    float gy = y * 2.0f - 1.0f;
    float gz = z * 2.0f - 1.0f;

    int ix0, ix1, iy0, iy1, iz0, iz1;
    float fx, fy, fz;
    prep_coord(gx, DIMX, ix0, ix1, fx);
    prep_coord(gy, DIMY, iy0, iy1, fy);
    prep_coord(gz, DIMZ, iz0, iz1, fz);

    float acc[28];
    #pragma unroll
    for (int c = 0; c < 28; c++) acc[c] = 0.0f;

    // seg 0: xy plane (rows: x, cols: y) * z vector -> F rows [0,48)
    do_seg((const float4*)(g_xyT + (ix0 * DIMY + iy0) * RNK),
           (const float4*)(g_xyT + (ix0 * DIMY + iy1) * RNK),
           (const float4*)(g_xyT + (ix1 * DIMY + iy0) * RNK),
           (const float4*)(g_xyT + (ix1 * DIMY + iy1) * RNK),
           (const float4*)(g_zvT + iz0 * RNK),
           (const float4*)(g_zvT + iz1 * RNK),
           fx, fy, fz, sBuf + 0 * RNK * 28, acc);

    // seg 1: xz plane (rows: x, cols: z) * y vector -> F rows [48,96)
    do_seg((const float4*)(g_xzT + (ix0 * DIMZ + iz0) * RNK),
           (const float4*)(g_xzT + (ix0 * DIMZ + iz1) * RNK),
           (const float4*)(g_xzT + (ix1 * DIMZ + iz0) * RNK),
           (const float4*)(g_xzT + (ix1 * DIMZ + iz1) * RNK),
           (const float4*)(g_yvT + iy0 * RNK),
           (const float4*)(g_yvT + iy1 * RNK),
           fx, fz, fy, sBuf + 1 * RNK * 28, acc);

    // seg 2: yz plane (rows: y, cols: z) * x vector -> F rows [96,144)
    do_seg((const float4*)(g_yzT + (iy0 * DIMZ + iz0) * RNK),
           (const float4*)(g_yzT + (iy0 * DIMZ + iz1) * RNK),
           (const float4*)(g_yzT + (iy1 * DIMZ + iz0) * RNK),
           (const float4*)(g_yzT + (iy1 * DIMZ + iz1) * RNK),
           (const float4*)(g_xvT + ix0 * RNK),
           (const float4*)(g_xvT + ix1 * RNK),
           fy, fz, fx, sBuf + 2 * RNK * 28, acc);

    __syncthreads();   // everyone is done reading sF

    if (p < NPTS) {
        #pragma unroll
        for (int c = 0; c < NC; c++) sBuf[tid * NC + c] = acc[c];
    }
    __syncthreads();

    int nvalid = NPTS - base;
    if (nvalid > 256) nvalid = 256;
    for (int i = tid; i < nvalid * NC; i += 256) {
        out[base * NC + i] = sBuf[i];
    }
}

extern "C" void kernel_launch(void* const* d_in, const int* in_sizes, int n_in,
                              void* d_out, int out_size)
{
    const float* xyz = (const float*)d_in[0];
    const float* xyp = (const float*)d_in[1];
    const float* xzp = (const float*)d_in[2];
    const float* yzp = (const float*)d_in[3];
    const float* xv  = (const float*)d_in[4];
    const float* yv  = (const float*)d_in[5];
    const float* zv  = (const float*)d_in[6];
    const float* fv  = (const float*)d_in[7];
    float* out = (float*)d_out;

    float *xyT, *xzT, *yzT, *xvT, *yvT, *zvT;
    cudaGetSymbolAddress((void**)&xyT, g_xyT);
    cudaGetSymbolAddress((void**)&xzT, g_xzT);
    cudaGetSymbolAddress((void**)&yzT, g_yzT);
    cudaGetSymbolAddress((void**)&xvT, g_xvT);
    cudaGetSymbolAddress((void**)&yvT, g_yvT);
    cudaGetSymbolAddress((void**)&zvT, g_zvT);

    const int pcells = DIMX * DIMY;             // 90000 (all planes same cell count)
    const int pblocks = (pcells + 127) / 128;   // 704
    const int vblocks = (DIMX + 127) / 128;     // 3

    transpose_kernel<<<pblocks, 128>>>(xyp, xyT, pcells);
    transpose_kernel<<<pblocks, 128>>>(xzp, xzT, DIMX * DIMZ);
    transpose_kernel<<<pblocks, 128>>>(yzp, yzT, DIMY * DIMZ);
    transpose_kernel<<<vblocks, 128>>>(xv, xvT, DIMX);
    transpose_kernel<<<vblocks, 128>>>(yv, yvT, DIMY);
    transpose_kernel<<<vblocks, 128>>>(zv, zvT, DIMZ);

    sample_kernel<<<(NPTS + 255) / 256, 256>>>(xyz, fv, out);
}

// round 2
// speedup vs baseline: 1.0569x; 1.0569x over previous
#include <cuda_runtime.h>

#define NPTS 1000000
#define DIMX 300
#define DIMY 300
#define DIMZ 300
#define RNK  48
#define NC   27

// Transposed scratch: planes [H*W][R], vectors [L][R]
__device__ __align__(16) float g_xyT[DIMX * DIMY * RNK];
__device__ __align__(16) float g_xzT[DIMX * DIMZ * RNK];
__device__ __align__(16) float g_yzT[DIMY * DIMZ * RNK];
__device__ __align__(16) float g_xvT[DIMX * RNK];
__device__ __align__(16) float g_yvT[DIMY * RNK];
__device__ __align__(16) float g_zvT[DIMZ * RNK];

// ---------- packed f32x2 helpers ----------
__device__ __forceinline__ unsigned long long pk2(float lo, float hi) {
    unsigned long long r;
    asm("mov.b64 %0, {%1, %2};" : "=l"(r) : "f"(lo), "f"(hi));
    return r;
}
__device__ __forceinline__ void upk2(unsigned long long v, float& lo, float& hi) {
    asm("mov.b64 {%0, %1}, %2;" : "=f"(lo), "=f"(hi) : "l"(v));
}
__device__ __forceinline__ unsigned long long f2mul(unsigned long long a, unsigned long long b) {
    unsigned long long d;
    asm("mul.rn.f32x2 %0, %1, %2;" : "=l"(d) : "l"(a), "l"(b));
    return d;
}
__device__ __forceinline__ unsigned long long f2fma(unsigned long long a, unsigned long long b,
                                                    unsigned long long c) {
    unsigned long long d;
    asm("fma.rn.f32x2 %0, %1, %2, %3;" : "=l"(d) : "l"(a), "l"(b), "l"(c));
    return d;
}

// ---------- one merged transpose kernel: [RNK][cells] -> [cells][RNK] ----------
// blocks 0..703: xy, 704..1407: xz, 1408..2111: yz, 2112..2120: vectors (3 each)
__global__ void __launch_bounds__(128) transpose_all(
    const float* __restrict__ xy, const float* __restrict__ xz,
    const float* __restrict__ yz, const float* __restrict__ xv,
    const float* __restrict__ yv, const float* __restrict__ zv)
{
    __shared__ float tile[RNK][129];
    int b = blockIdx.x;
    const float* src;
    float* dst;
    int cells, base;
    if (b < 704)        { src = xy; dst = g_xyT; cells = DIMX * DIMY; base = b * 128; }
    else if (b < 1408)  { src = xz; dst = g_xzT; cells = DIMX * DIMZ; base = (b - 704) * 128; }
    else if (b < 2112)  { src = yz; dst = g_yzT; cells = DIMY * DIMZ; base = (b - 1408) * 128; }
    else {
        int vb = b - 2112;
        int vi = vb / 3;
        base = (vb % 3) * 128;
        cells = DIMX;
        src = (vi == 0) ? xv : ((vi == 1) ? yv : zv);
        dst = (vi == 0) ? g_xvT : ((vi == 1) ? g_yvT : g_zvT);
    }

    int t = threadIdx.x;
    int nc = cells - base;
    if (nc > 128) nc = 128;

    #pragma unroll
    for (int r = 0; r < RNK; r++) {
        if (t < nc) tile[r][t] = src[r * cells + base + t];
    }
    __syncthreads();
    for (int i = t; i < nc * RNK; i += 128) {
        int cl = i / RNK;
        int r  = i - cl * RNK;
        dst[(base + cl) * RNK + r] = tile[r][cl];
    }
}

// ---------- fused segment: bilinear(plane) * lerp(vec) -> packed FMA into acc[14] ----------
__device__ __forceinline__ void do_seg2(
    const ulonglong2* __restrict__ p00, const ulonglong2* __restrict__ p01,
    const ulonglong2* __restrict__ p10, const ulonglong2* __restrict__ p11,
    const ulonglong2* __restrict__ v0p, const ulonglong2* __restrict__ v1p,
    float fh, float fw, float fv,
    const float* __restrict__ sFrow, unsigned long long* acc)
{
    float w00 = (1.0f - fh) * (1.0f - fw);
    float w01 = (1.0f - fh) * fw;
    float w10 = fh * (1.0f - fw);
    float w11 = fh * fw;
    unsigned long long W00 = pk2(w00, w00), W01 = pk2(w01, w01);
    unsigned long long W10 = pk2(w10, w10), W11 = pk2(w11, w11);
    unsigned long long FV  = pk2(fv, fv),  GV  = pk2(1.0f - fv, 1.0f - fv);

    #pragma unroll 2
    for (int k = 0; k < RNK / 4; k++) {   // each iter: ranks 4k..4k+3
        ulonglong2 a = p00[k];
        ulonglong2 b = p01[k];
        ulonglong2 c = p10[k];
        ulonglong2 d = p11[k];
        ulonglong2 u = v0p[k];
        ulonglong2 w = v1p[k];

        // fe for ranks (4k,4k+1) packed
        unsigned long long t0 = f2mul(W00, a.x);
        t0 = f2fma(W01, b.x, t0);
        t0 = f2fma(W10, c.x, t0);
        t0 = f2fma(W11, d.x, t0);
        unsigned long long v0 = f2fma(FV, w.x, f2mul(GV, u.x));
        unsigned long long fe01 = f2mul(t0, v0);

        // fe for ranks (4k+2,4k+3) packed
        unsigned long long t1 = f2mul(W00, a.y);
        t1 = f2fma(W01, b.y, t1);
        t1 = f2fma(W10, c.y, t1);
        t1 = f2fma(W11, d.y, t1);
        unsigned long long v1 = f2fma(FV, w.y, f2mul(GV, u.y));
        unsigned long long fe23 = f2mul(t1, v1);

        float f0, f1, f2, f3;
        upk2(fe01, f0, f1);
        upk2(fe23, f2, f3);
        float fs[4] = {f0, f1, f2, f3};

        #pragma unroll
        for (int j = 0; j < 4; j++) {
            unsigned long long F2 = pk2(fs[j], fs[j]);
            const ulonglong2* Fr = (const ulonglong2*)(sFrow + (k * 4 + j) * 28);
            #pragma unroll
            for (int m = 0; m < 7; m++) {
                ulonglong2 q = Fr[m];
                acc[m * 2 + 0] = f2fma(F2, q.x, acc[m * 2 + 0]);
                acc[m * 2 + 1] = f2fma(F2, q.y, acc[m * 2 + 1]);
            }
        }
    }
}

__device__ __forceinline__ void prep_coord(float g, int L, int& i0, int& i1, float& f)
{
    float t  = (g + 1.0f) * 0.5f;
    float ih = t * (float)(L - 1);
    int i = (int)floorf(ih);
    i = max(0, min(i, L - 1));
    i0 = i;
    i1 = min(i + 1, L - 1);
    f = ih - (float)i;
}

__global__ void __launch_bounds__(256) sample_kernel(
    const float* __restrict__ xyz, const float* __restrict__ fvec,
    float* __restrict__ out)
{
    // sBuf: first the padded F (144 rows x 28 floats = 4032), then output staging (256*27)
    __shared__ __align__(16) float sBuf[256 * NC];
    __shared__ float sXYZ[256 * 3];

    int tid  = threadIdx.x;
    int base = blockIdx.x * 256;

    for (int i = tid; i < 144 * 28; i += 256) {
        int r = i / 28;
        int c = i - r * 28;
        sBuf[i] = (c < NC) ? fvec[r * NC + c] : 0.0f;
    }
    for (int i = tid; i < 768; i += 256) {
        int g = base * 3 + i;
        sXYZ[i] = (g < NPTS * 3) ? xyz[g] : 0.25f;
    }
    __syncthreads();

    int p = base + tid;
    float x = sXYZ[tid * 3 + 0];
    float y = sXYZ[tid * 3 + 1];
    float z = sXYZ[tid * 3 + 2];

    float gx = x * 2.0f - 1.0f;
    float gy = y * 2.0f - 1.0f;
    float gz = z * 2.0f - 1.0f;

    int ix0, ix1, iy0, iy1, iz0, iz1;
    float fx, fy, fz;
    prep_coord(gx, DIMX, ix0, ix1, fx);
    prep_coord(gy, DIMY, iy0, iy1, fy);
    prep_coord(gz, DIMZ, iz0, iz1, fz);

    unsigned long long acc[14];
    #pragma unroll
    for (int c = 0; c < 14; c++) acc[c] = 0ULL;

    // seg 0: xy plane (rows x, cols y) * z vector -> F rows [0,48)
    do_seg2((const ulonglong2*)(g_xyT + (ix0 * DIMY + iy0) * RNK),
            (const ulonglong2*)(g_xyT + (ix0 * DIMY + iy1) * RNK),
            (const ulonglong2*)(g_xyT + (ix1 * DIMY + iy0) * RNK),
            (const ulonglong2*)(g_xyT + (ix1 * DIMY + iy1) * RNK),
            (const ulonglong2*)(g_zvT + iz0 * RNK),
            (const ulonglong2*)(g_zvT + iz1 * RNK),
            fx, fy, fz, sBuf + 0 * RNK * 28, acc);

    // seg 1: xz plane (rows x, cols z) * y vector -> F rows [48,96)
    do_seg2((const ulonglong2*)(g_xzT + (ix0 * DIMZ + iz0) * RNK),
            (const ulonglong2*)(g_xzT + (ix0 * DIMZ + iz1) * RNK),
            (const ulonglong2*)(g_xzT + (ix1 * DIMZ + iz0) * RNK),
            (const ulonglong2*)(g_xzT + (ix1 * DIMZ + iz1) * RNK),
            (const ulonglong2*)(g_yvT + iy0 * RNK),
            (const ulonglong2*)(g_yvT + iy1 * RNK),
            fx, fz, fy, sBuf + 1 * RNK * 28, acc);

    // seg 2: yz plane (rows y, cols z) * x vector -> F rows [96,144)
    do_seg2((const ulonglong2*)(g_yzT + (iy0 * DIMZ + iz0) * RNK),
            (const ulonglong2*)(g_yzT + (iy0 * DIMZ + iz1) * RNK),
            (const ulonglong2*)(g_yzT + (iy1 * DIMZ + iz0) * RNK),
            (const ulonglong2*)(g_yzT + (iy1 * DIMZ + iz1) * RNK),
            (const ulonglong2*)(g_xvT + ix0 * RNK),
            (const ulonglong2*)(g_xvT + ix1 * RNK),
            fy, fz, fx, sBuf + 2 * RNK * 28, acc);

    __syncthreads();   // everyone done reading sF

    if (p < NPTS) {
        float o[28];
        #pragma unroll
        for (int m = 0; m < 14; m++) upk2(acc[m], o[2 * m], o[2 * m + 1]);
        #pragma unroll
        for (int c = 0; c < NC; c++) sBuf[tid * NC + c] = o[c];
    }
    __syncthreads();

    int nvalid = NPTS - base;
    if (nvalid > 256) nvalid = 256;
    for (int i = tid; i < nvalid * NC; i += 256) {
        out[base * NC + i] = sBuf[i];
    }
}

extern "C" void kernel_launch(void* const* d_in, const int* in_sizes, int n_in,
                              void* d_out, int out_size)
{
    const float* xyz = (const float*)d_in[0];
    const float* xyp = (const float*)d_in[1];
    const float* xzp = (const float*)d_in[2];
    const float* yzp = (const float*)d_in[3];
    const float* xv  = (const float*)d_in[4];
    const float* yv  = (const float*)d_in[5];
    const float* zv  = (const float*)d_in[6];
    const float* fv  = (const float*)d_in[7];
    float* out = (float*)d_out;

    transpose_all<<<2121, 128>>>(xyp, xzp, yzp, xv, yv, zv);
    sample_kernel<<<(NPTS + 255) / 256, 256>>>(xyz, fv, out);
}

// round 3
// speedup vs baseline: 1.1425x; 1.0811x over previous
#include <cuda_runtime.h>

#define NPTS 1000000
#define DIMX 300
#define DIMY 300
#define DIMZ 300
#define RNK  48
#define NC   27

// Transposed scratch: planes [H*W][R], vectors [L][R]
__device__ __align__(16) float g_xyT[DIMX * DIMY * RNK];
__device__ __align__(16) float g_xzT[DIMX * DIMZ * RNK];
__device__ __align__(16) float g_yzT[DIMY * DIMZ * RNK];
__device__ __align__(16) float g_xvT[DIMX * RNK];
__device__ __align__(16) float g_yvT[DIMY * RNK];
__device__ __align__(16) float g_zvT[DIMZ * RNK];

// ---------- packed f32x2 helpers ----------
__device__ __forceinline__ unsigned long long pk2(float lo, float hi) {
    unsigned long long r;
    asm("mov.b64 %0, {%1, %2};" : "=l"(r) : "f"(lo), "f"(hi));
    return r;
}
__device__ __forceinline__ void upk2(unsigned long long v, float& lo, float& hi) {
    asm("mov.b64 {%0, %1}, %2;" : "=f"(lo), "=f"(hi) : "l"(v));
}
__device__ __forceinline__ unsigned long long f2mul(unsigned long long a, unsigned long long b) {
    unsigned long long d;
    asm("mul.rn.f32x2 %0, %1, %2;" : "=l"(d) : "l"(a), "l"(b));
    return d;
}
__device__ __forceinline__ unsigned long long f2add(unsigned long long a, unsigned long long b) {
    unsigned long long d;
    asm("add.rn.f32x2 %0, %1, %2;" : "=l"(d) : "l"(a), "l"(b));
    return d;
}
__device__ __forceinline__ unsigned long long f2fma(unsigned long long a, unsigned long long b,
                                                    unsigned long long c) {
    unsigned long long d;
    asm("fma.rn.f32x2 %0, %1, %2, %3;" : "=l"(d) : "l"(a), "l"(b), "l"(c));
    return d;
}

// ---------- one merged transpose kernel: [RNK][cells] -> [cells][RNK] ----------
__global__ void __launch_bounds__(128) transpose_all(
    const float* __restrict__ xy, const float* __restrict__ xz,
    const float* __restrict__ yz, const float* __restrict__ xv,
    const float* __restrict__ yv, const float* __restrict__ zv)
{
    __shared__ float tile[RNK][129];
    int b = blockIdx.x;
    const float* src;
    float* dst;
    int cells, base;
    if (b < 704)        { src = xy; dst = g_xyT; cells = DIMX * DIMY; base = b * 128; }
    else if (b < 1408)  { src = xz; dst = g_xzT; cells = DIMX * DIMZ; base = (b - 704) * 128; }
    else if (b < 2112)  { src = yz; dst = g_yzT; cells = DIMY * DIMZ; base = (b - 1408) * 128; }
    else {
        int vb = b - 2112;
        int vi = vb / 3;
        base = (vb % 3) * 128;
        cells = DIMX;
        src = (vi == 0) ? xv : ((vi == 1) ? yv : zv);
        dst = (vi == 0) ? g_xvT : ((vi == 1) ? g_yvT : g_zvT);
    }

    int t = threadIdx.x;
    int nc = cells - base;
    if (nc > 128) nc = 128;

    #pragma unroll
    for (int r = 0; r < RNK; r++) {
        if (t < nc) tile[r][t] = src[r * cells + base + t];
    }
    __syncthreads();
    for (int i = t; i < nc * RNK; i += 128) {
        int cl = i / RNK;
        int r  = i - cl * RNK;
        dst[(base + cl) * RNK + r] = tile[r][cl];
    }
}

__device__ __forceinline__ void prep_coord(float g, int L, int& i0, int& i1, float& f)
{
    float t  = (g + 1.0f) * 0.5f;
    float ih = t * (float)(L - 1);
    int i = (int)floorf(ih);
    i = max(0, min(i, L - 1));
    i0 = i;
    i1 = min(i + 1, L - 1);
    f = ih - (float)i;
}

// One segment, cooperative: lane handles ranks 16*i + 4*s + {0..3} for i=0..2.
// sF rows are stored s/j-swapped, so the row for (i, s, j) lives at slot
// seg*48 + 16*i + 4*j + s  (consecutive slots across the 4 lanes -> no bank conflicts).
__device__ __forceinline__ void do_seg_coop(
    const ulonglong2* __restrict__ p00, const ulonglong2* __restrict__ p01,
    const ulonglong2* __restrict__ p10, const ulonglong2* __restrict__ p11,
    const ulonglong2* __restrict__ v0p, const ulonglong2* __restrict__ v1p,
    float fh, float fw, float fv, int s,
    const float* __restrict__ sFseg, unsigned long long* acc)
{
    float w00 = (1.0f - fh) * (1.0f - fw);
    float w01 = (1.0f - fh) * fw;
    float w10 = fh * (1.0f - fw);
    float w11 = fh * fw;
    unsigned long long W00 = pk2(w00, w00), W01 = pk2(w01, w01);
    unsigned long long W10 = pk2(w10, w10), W11 = pk2(w11, w11);
    unsigned long long FV  = pk2(fv, fv),  GV  = pk2(1.0f - fv, 1.0f - fv);

    #pragma unroll
    for (int i = 0; i < 3; i++) {
        int idx = i * 4 + s;          // ulonglong2 index = byte offset (i*64 + s*16)
        ulonglong2 a = p00[idx];
        ulonglong2 b = p01[idx];
        ulonglong2 c = p10[idx];
        ulonglong2 d = p11[idx];
        ulonglong2 u = v0p[idx];
        ulonglong2 w = v1p[idx];

        unsigned long long t0 = f2mul(W00, a.x);
        t0 = f2fma(W01, b.x, t0);
        t0 = f2fma(W10, c.x, t0);
        t0 = f2fma(W11, d.x, t0);
        unsigned long long v0 = f2fma(FV, w.x, f2mul(GV, u.x));
        unsigned long long fe01 = f2mul(t0, v0);

        unsigned long long t1 = f2mul(W00, a.y);
        t1 = f2fma(W01, b.y, t1);
        t1 = f2fma(W10, c.y, t1);
        t1 = f2fma(W11, d.y, t1);
        unsigned long long v1 = f2fma(FV, w.y, f2mul(GV, u.y));
        unsigned long long fe23 = f2mul(t1, v1);

        float f0, f1, f2, f3;
        upk2(fe01, f0, f1);
        upk2(fe23, f2, f3);
        float fs[4] = {f0, f1, f2, f3};

        #pragma unroll
        for (int j = 0; j < 4; j++) {
            unsigned long long F2 = pk2(fs[j], fs[j]);
            const ulonglong2* Fr =
                (const ulonglong2*)(sFseg + (i * 16 + j * 4 + s) * 28);
            #pragma unroll
            for (int m = 0; m < 7; m++) {
                ulonglong2 q = Fr[m];
                acc[m * 2 + 0] = f2fma(F2, q.x, acc[m * 2 + 0]);
                acc[m * 2 + 1] = f2fma(F2, q.y, acc[m * 2 + 1]);
            }
        }
    }
}

__global__ void __launch_bounds__(256) sample_kernel(
    const float* __restrict__ xyz, const float* __restrict__ fvec,
    float* __restrict__ out)
{
    // sF: padded+permuted F (144 rows x 28 floats). Reused as output staging
    // (64 pts x 28) after all matvec reads are done.
    __shared__ __align__(16) float sF[144 * 28];
    __shared__ float sXYZ[64 * 3];

    int tid  = threadIdx.x;
    int lane = tid & 31;
    int warp = tid >> 5;
    int s    = lane & 3;        // sub-lane within point group
    int pw   = lane >> 2;       // point within warp (0..7)
    int pp   = warp * 8 + pw;   // point within block (0..63)
    int base = blockIdx.x * 64;

    // Load F with rows s/j-swapped within each 16-row group, pad 27 -> 28.
    for (int i = tid; i < 144 * 28; i += 256) {
        int r = i / 28;
        int c = i - r * 28;
        int rp = (r & ~15) | ((r & 3) << 2) | ((r >> 2) & 3);   // sigma(r)
        sF[rp * 28 + c] = (c < NC) ? fvec[r * NC + c] : 0.0f;
    }
    if (tid < 192) sXYZ[tid] = xyz[base * 3 + tid];
    __syncthreads();

    float x = sXYZ[pp * 3 + 0];
    float y = sXYZ[pp * 3 + 1];
    float z = sXYZ[pp * 3 + 2];

    float gx = x * 2.0f - 1.0f;
    float gy = y * 2.0f - 1.0f;
    float gz = z * 2.0f - 1.0f;

    int ix0, ix1, iy0, iy1, iz0, iz1;
    float fx, fy, fz;
    prep_coord(gx, DIMX, ix0, ix1, fx);
    prep_coord(gy, DIMY, iy0, iy1, fy);
    prep_coord(gz, DIMZ, iz0, iz1, fz);

    unsigned long long acc[14];
    #pragma unroll
    for (int c = 0; c < 14; c++) acc[c] = 0ULL;

    // seg 0: xy plane * z vector
    do_seg_coop((const ulonglong2*)(g_xyT + (ix0 * DIMY + iy0) * RNK),
                (const ulonglong2*)(g_xyT + (ix0 * DIMY + iy1) * RNK),
                (const ulonglong2*)(g_xyT + (ix1 * DIMY + iy0) * RNK),
                (const ulonglong2*)(g_xyT + (ix1 * DIMY + iy1) * RNK),
                (const ulonglong2*)(g_zvT + iz0 * RNK),
                (const ulonglong2*)(g_zvT + iz1 * RNK),
                fx, fy, fz, s, sF + 0 * RNK * 28, acc);

    // seg 1: xz plane * y vector
    do_seg_coop((const ulonglong2*)(g_xzT + (ix0 * DIMZ + iz0) * RNK),
                (const ulonglong2*)(g_xzT + (ix0 * DIMZ + iz1) * RNK),
                (const ulonglong2*)(g_xzT + (ix1 * DIMZ + iz0) * RNK),
                (const ulonglong2*)(g_xzT + (ix1 * DIMZ + iz1) * RNK),
                (const ulonglong2*)(g_yvT + iy0 * RNK),
                (const ulonglong2*)(g_yvT + iy1 * RNK),
                fx, fz, fy, s, sF + 1 * RNK * 28, acc);

    // seg 2: yz plane * x vector
    do_seg_coop((const ulonglong2*)(g_yzT + (iy0 * DIMZ + iz0) * RNK),
                (const ulonglong2*)(g_yzT + (iy0 * DIMZ + iz1) * RNK),
                (const ulonglong2*)(g_yzT + (iy1 * DIMZ + iz0) * RNK),
                (const ulonglong2*)(g_yzT + (iy1 * DIMZ + iz1) * RNK),
                (const ulonglong2*)(g_xvT + ix0 * RNK),
                (const ulonglong2*)(g_xvT + ix1 * RNK),
                fy, fz, fx, s, sF + 2 * RNK * 28, acc);

    // Reduce partials across the 4 lanes of each point.
    #pragma unroll
    for (int m = 0; m < 14; m++) {
        unsigned long long t = __shfl_xor_sync(0xffffffffu, acc[m], 1);
        acc[m] = f2add(acc[m], t);
        t = __shfl_xor_sync(0xffffffffu, acc[m], 2);
        acc[m] = f2add(acc[m], t);
    }

    __syncthreads();   // all matvec reads of sF complete; reuse as staging

    if (s == 0) {
        unsigned long long* dst = (unsigned long long*)(sF + pp * 28);
        #pragma unroll
        for (int m = 0; m < 14; m++) dst[m] = acc[m];  // slot 27 is junk, never read
    }
    __syncthreads();

    #pragma unroll 2
    for (int i = tid; i < 64 * NC; i += 256) {
        int pt = i / NC;
        int c  = i - pt * NC;
        out[base * NC + i] = sF[pt * 28 + c];
    }
}

extern "C" void kernel_launch(void* const* d_in, const int* in_sizes, int n_in,
                              void* d_out, int out_size)
{
    const float* xyz = (const float*)d_in[0];
    const float* xyp = (const float*)d_in[1];
    const float* xzp = (const float*)d_in[2];
    const float* yzp = (const float*)d_in[3];
    const float* xv  = (const float*)d_in[4];
    const float* yv  = (const float*)d_in[5];
    const float* zv  = (const float*)d_in[6];
    const float* fv  = (const float*)d_in[7];
    float* out = (float*)d_out;

    transpose_all<<<2121, 128>>>(xyp, xzp, yzp, xv, yv, zv);
    sample_kernel<<<NPTS / 64, 256>>>(xyz, fv, out);
}

// round 4
// speedup vs baseline: 1.2451x; 1.0898x over previous
#include <cuda_runtime.h>
#include <cuda_fp16.h>

#define NPTS 1000000
#define DX 300
#define DY 300
#define DZ 300
#define RNK  48
#define PSTR 64    // padded halves per plane cell (128 B, line-aligned)
#define NC   27

// fp16 planes (cell-major, 64-half padded rows), fp32 vectors (cell-major, 48 floats)
__device__ __align__(16) __half g_xyH[DX * DY * PSTR];
__device__ __align__(16) __half g_xzH[DX * DZ * PSTR];
__device__ __align__(16) __half g_yzH[DY * DZ * PSTR];
__device__ __align__(16) float  g_xvT[DX * RNK];
__device__ __align__(16) float  g_yvT[DY * RNK];
__device__ __align__(16) float  g_zvT[DZ * RNK];

typedef unsigned long long u64;

// ---------- packed f32x2 helpers ----------
__device__ __forceinline__ u64 pk2(float lo, float hi) {
    u64 r;
    asm("mov.b64 %0, {%1, %2};" : "=l"(r) : "f"(lo), "f"(hi));
    return r;
}
__device__ __forceinline__ void upk2(u64 v, float& lo, float& hi) {
    asm("mov.b64 {%0, %1}, %2;" : "=f"(lo), "=f"(hi) : "l"(v));
}
__device__ __forceinline__ u64 f2mul(u64 a, u64 b) {
    u64 d;
    asm("mul.rn.f32x2 %0, %1, %2;" : "=l"(d) : "l"(a), "l"(b));
    return d;
}
__device__ __forceinline__ u64 f2add(u64 a, u64 b) {
    u64 d;
    asm("add.rn.f32x2 %0, %1, %2;" : "=l"(d) : "l"(a), "l"(b));
    return d;
}
__device__ __forceinline__ u64 f2fma(u64 a, u64 b, u64 c) {
    u64 d;
    asm("fma.rn.f32x2 %0, %1, %2, %3;" : "=l"(d) : "l"(a), "l"(b), "l"(c));
    return d;
}
__device__ __forceinline__ u64 h2f2(unsigned int h) {
    float2 f = __half22float2(*(__half2*)&h);
    return pk2(f.x, f.y);
}

// ---------- merged transpose/convert: [RNK][cells] -> fp16 [cells][PSTR] (planes)
//                                                   -> fp32 [cells][RNK]  (vectors)
__global__ void __launch_bounds__(128) transpose_all(
    const float* __restrict__ xy, const float* __restrict__ xz,
    const float* __restrict__ yz, const float* __restrict__ xv,
    const float* __restrict__ yv, const float* __restrict__ zv)
{
    __shared__ float tile[RNK][129];
    int b = blockIdx.x;
    int t = threadIdx.x;

    if (b < 2112) {
        const float* src;
        __half* dst;
        int base;
        const int cells = DX * DY;     // 90000 for every plane
        if (b < 704)       { src = xy; dst = g_xyH; base = b * 128; }
        else if (b < 1408) { src = xz; dst = g_xzH; base = (b - 704) * 128; }
        else               { src = yz; dst = g_yzH; base = (b - 1408) * 128; }

        int nc = cells - base;
        if (nc > 128) nc = 128;

        #pragma unroll
        for (int r = 0; r < RNK; r++) {
            if (t < nc) tile[r][t] = src[r * cells + base + t];
        }
        __syncthreads();
        __half2* dst2 = (__half2*)dst;
        for (int i = t; i < nc * 32; i += 128) {   // 32 half2 per cell
            int cl = i >> 5;
            int p  = i & 31;
            float lo = (2 * p     < RNK) ? tile[2 * p][cl]     : 0.0f;
            float hi = (2 * p + 1 < RNK) ? tile[2 * p + 1][cl] : 0.0f;
            dst2[(u64)(base + cl) * 32 + p] = __floats2half2_rn(lo, hi);
        }
    } else {
        int vb = b - 2112;
        int vi = vb / 3;
        int base = (vb % 3) * 128;
        const int cells = DX;          // 300 for every vector
        const float* src = (vi == 0) ? xv : ((vi == 1) ? yv : zv);
        float* dst = (vi == 0) ? g_xvT : ((vi == 1) ? g_yvT : g_zvT);

        int nc = cells - base;
        if (nc > 128) nc = 128;
        if (nc <= 0) return;

        #pragma unroll
        for (int r = 0; r < RNK; r++) {
            if (t < nc) tile[r][t] = src[r * cells + base + t];
        }
        __syncthreads();
        for (int i = t; i < nc * RNK; i += 128) {
            int cl = i / RNK;
            int r  = i - cl * RNK;
            dst[(base + cl) * RNK + r] = tile[r][cl];
        }
    }
}

__device__ __forceinline__ void prep_coord(float g, int L, int& i0, int& i1, float& f)
{
    float t  = (g + 1.0f) * 0.5f;
    float ih = t * (float)(L - 1);
    int i = (int)floorf(ih);
    i = max(0, min(i, L - 1));
    i0 = i;
    i1 = min(i + 1, L - 1);
    f = ih - (float)i;
}

// one plane-corner gather for lane s: 16B (ranks 8s..8s+7) + 8B (ranks 32+4s..+3)
struct PC { uint4 a; uint2 b; };
__device__ __forceinline__ PC ldpc(const __half* cell, int s)
{
    PC r;
    r.a = *(const uint4*)((const char*)cell + s * 16);
    r.b = *(const uint2*)((const char*)cell + 64 + s * 8);
    return r;
}

// matvec: acc += f * Frow[0..27]
__device__ __forceinline__ void mv(const float* __restrict__ row, float f, u64* acc)
{
    u64 F2 = pk2(f, f);
    const ulonglong2* Fr = (const ulonglong2*)row;
    #pragma unroll
    for (int m = 0; m < 7; m++) {
        ulonglong2 q = Fr[m];
        acc[m * 2 + 0] = f2fma(F2, q.x, acc[m * 2 + 0]);
        acc[m * 2 + 1] = f2fma(F2, q.y, acc[m * 2 + 1]);
    }
}

// one segment: fp16 bilinear corners (already loaded) * fp32 vec lerp -> matvec
__device__ __forceinline__ void do_seg(
    const PC& c00, const PC& c01, const PC& c10, const PC& c11,
    const float* __restrict__ vbase0, const float* __restrict__ vbase1, int s,
    float fh, float fw, float fv,
    const float* __restrict__ sFseg, u64* acc)
{
    float w00 = (1.0f - fh) * (1.0f - fw);
    float w01 = (1.0f - fh) * fw;
    float w10 = fh * (1.0f - fw);
    float w11 = fh * fw;
    u64 W00 = pk2(w00, w00), W01 = pk2(w01, w01);
    u64 W10 = pk2(w10, w10), W11 = pk2(w11, w11);
    u64 FV  = pk2(fv, fv),  GV = pk2(1.0f - fv, 1.0f - fv);

    // vectors: chunkA ranks 8s..8s+7, chunkB ranks 32+4s..+3
    float4 u0 = *(const float4*)(vbase0 + 8 * s);
    float4 u1 = *(const float4*)(vbase0 + 8 * s + 4);
    float4 ub = *(const float4*)(vbase0 + 32 + 4 * s);
    float4 q0 = *(const float4*)(vbase1 + 8 * s);
    float4 q1 = *(const float4*)(vbase1 + 8 * s + 4);
    float4 qb = *(const float4*)(vbase1 + 32 + 4 * s);

    // ---- chunk A: 4 packed pairs (ranks 8s+2k, 8s+2k+1) ----
    const unsigned int* a00 = (const unsigned int*)&c00.a;
    const unsigned int* a01 = (const unsigned int*)&c01.a;
    const unsigned int* a10 = (const unsigned int*)&c10.a;
    const unsigned int* a11 = (const unsigned int*)&c11.a;
    u64 UA[4] = { pk2(u0.x, u0.y), pk2(u0.z, u0.w), pk2(u1.x, u1.y), pk2(u1.z, u1.w) };
    u64 QA[4] = { pk2(q0.x, q0.y), pk2(q0.z, q0.w), pk2(q1.x, q1.y), pk2(q1.z, q1.w) };

    #pragma unroll
    for (int k = 0; k < 4; k++) {
        u64 t = f2mul(W00, h2f2(a00[k]));
        t = f2fma(W01, h2f2(a01[k]), t);
        t = f2fma(W10, h2f2(a10[k]), t);
        t = f2fma(W11, h2f2(a11[k]), t);
        u64 v = f2fma(FV, QA[k], f2mul(GV, UA[k]));
        u64 fe = f2mul(t, v);
        float flo, fhi;
        upk2(fe, flo, fhi);
        // rows: e=2k -> slot 8k+s ; e=2k+1 -> slot 8k+4+s
        mv(sFseg + (8 * k + s) * 28, flo, acc);
        mv(sFseg + (8 * k + 4 + s) * 28, fhi, acc);
    }

    // ---- chunk B: 2 packed pairs (ranks 32+4s+2k, +2k+1) ----
    const unsigned int* b00 = (const unsigned int*)&c00.b;
    const unsigned int* b01 = (const unsigned int*)&c01.b;
    const unsigned int* b10 = (const unsigned int*)&c10.b;
    const unsigned int* b11 = (const unsigned int*)&c11.b;
    u64 UB[2] = { pk2(ub.x, ub.y), pk2(ub.z, ub.w) };
    u64 QB[2] = { pk2(qb.x, qb.y), pk2(qb.z, qb.w) };

    #pragma unroll
    for (int k = 0; k < 2; k++) {
        u64 t = f2mul(W00, h2f2(b00[k]));
        t = f2fma(W01, h2f2(b01[k]), t);
        t = f2fma(W10, h2f2(b10[k]), t);
        t = f2fma(W11, h2f2(b11[k]), t);
        u64 v = f2fma(FV, QB[k], f2mul(GV, UB[k]));
        u64 fe = f2mul(t, v);
        float flo, fhi;
        upk2(fe, flo, fhi);
        // rows: slot 32+8k+s and 36+8k+s
        mv(sFseg + (32 + 8 * k + s) * 28, flo, acc);
        mv(sFseg + (36 + 8 * k + s) * 28, fhi, acc);
    }
}

__global__ void __launch_bounds__(256, 2) sample_kernel(
    const float* __restrict__ xyz, const float* __restrict__ fvec,
    float* __restrict__ out)
{
    // sF: permuted padded F (144 x 28). Reused as output staging after matvec.
    __shared__ __align__(16) float sF[144 * 28];
    __shared__ float sXYZ[64 * 3];

    int tid  = threadIdx.x;
    int lane = tid & 31;
    int warp = tid >> 5;
    int s    = lane & 3;
    int pw   = lane >> 2;
    int pp   = warp * 8 + pw;
    int base = blockIdx.x * 64;

    // Permutation: within each 48-row segment block, rows rr<32 (chunkA, rr=8s+e)
    // go to slot 4e+s; rows rr>=32 (chunkB, rr=32+4s+e) go to slot 32+4e+s.
    for (int i = tid; i < 144 * 28; i += 256) {
        int r = i / 28;
        int c = i - r * 28;
        int seg = r / 48;
        int rr  = r - seg * 48;
        int slot;
        if (rr < 32) slot = seg * 48 + ((rr & 7) << 2) + (rr >> 3);
        else { int tb = rr - 32; slot = seg * 48 + 32 + ((tb & 3) << 2) + (tb >> 2); }
        sF[slot * 28 + c] = (c < NC) ? fvec[r * NC + c] : 0.0f;
    }
    if (tid < 192) sXYZ[tid] = xyz[base * 3 + tid];
    __syncthreads();

    float x = sXYZ[pp * 3 + 0];
    float y = sXYZ[pp * 3 + 1];
    float z = sXYZ[pp * 3 + 2];

    int ix0, ix1, iy0, iy1, iz0, iz1;
    float fx, fy, fz;
    prep_coord(x * 2.0f - 1.0f, DX, ix0, ix1, fx);
    prep_coord(y * 2.0f - 1.0f, DY, iy0, iy1, fy);
    prep_coord(z * 2.0f - 1.0f, DZ, iz0, iz1, fz);

    u64 acc[14];
    #pragma unroll
    for (int c = 0; c < 14; c++) acc[c] = 0ULL;

    // ---- software-pipelined gathers: load seg k+1 before computing seg k ----
    // seg0: xy plane
    PC c00 = ldpc(g_xyH + (u64)(ix0 * DY + iy0) * PSTR, s);
    PC c01 = ldpc(g_xyH + (u64)(ix0 * DY + iy1) * PSTR, s);
    PC c10 = ldpc(g_xyH + (u64)(ix1 * DY + iy0) * PSTR, s);
    PC c11 = ldpc(g_xyH + (u64)(ix1 * DY + iy1) * PSTR, s);

    // prefetch seg1: xz plane
    PC n00 = ldpc(g_xzH + (u64)(ix0 * DZ + iz0) * PSTR, s);
    PC n01 = ldpc(g_xzH + (u64)(ix0 * DZ + iz1) * PSTR, s);
    PC n10 = ldpc(g_xzH + (u64)(ix1 * DZ + iz0) * PSTR, s);
    PC n11 = ldpc(g_xzH + (u64)(ix1 * DZ + iz1) * PSTR, s);

    do_seg(c00, c01, c10, c11, g_zvT + iz0 * RNK, g_zvT + iz1 * RNK, s,
           fx, fy, fz, sF, acc);

    // prefetch seg2: yz plane
    c00 = ldpc(g_yzH + (u64)(iy0 * DZ + iz0) * PSTR, s);
    c01 = ldpc(g_yzH + (u64)(iy0 * DZ + iz1) * PSTR, s);
    c10 = ldpc(g_yzH + (u64)(iy1 * DZ + iz0) * PSTR, s);
    c11 = ldpc(g_yzH + (u64)(iy1 * DZ + iz1) * PSTR, s);

    do_seg(n00, n01, n10, n11, g_yvT + iy0 * RNK, g_yvT + iy1 * RNK, s,
           fx, fz, fy, sF + 48 * 28, acc);

    do_seg(c00, c01, c10, c11, g_xvT + ix0 * RNK, g_xvT + ix1 * RNK, s,
           fy, fz, fx, sF + 96 * 28, acc);

    // reduce across the 4 lanes of each point
    #pragma unroll
    for (int m = 0; m < 14; m++) {
        u64 t = __shfl_xor_sync(0xffffffffu, acc[m], 1);
        acc[m] = f2add(acc[m], t);
        t = __shfl_xor_sync(0xffffffffu, acc[m], 2);
        acc[m] = f2add(acc[m], t);
    }

    __syncthreads();   // all matvec reads of sF done; reuse as staging

    if (s == 0) {
        u64* dst = (u64*)(sF + pp * 28);
        #pragma unroll
        for (int m = 0; m < 14; m++) dst[m] = acc[m];  // slot 27 junk, never read
    }
    __syncthreads();

    #pragma unroll 2
    for (int i = tid; i < 64 * NC; i += 256) {
        int pt = i / NC;
        int c  = i - pt * NC;
        out[base * NC + i] = sF[pt * 28 + c];
    }
}

extern "C" void kernel_launch(void* const* d_in, const int* in_sizes, int n_in,
                              void* d_out, int out_size)
{
    const float* xyz = (const float*)d_in[0];
    const float* xyp = (const float*)d_in[1];
    const float* xzp = (const float*)d_in[2];
    const float* yzp = (const float*)d_in[3];
    const float* xv  = (const float*)d_in[4];
    const float* yv  = (const float*)d_in[5];
    const float* zv  = (const float*)d_in[6];
    const float* fv  = (const float*)d_in[7];
    float* out = (float*)d_out;

    transpose_all<<<2121, 128>>>(xyp, xzp, yzp, xv, yv, zv);
    sample_kernel<<<NPTS / 64, 256>>>(xyz, fv, out);
}